// round 9
// baseline (speedup 1.0000x reference)
#include <cuda_runtime.h>
#include <cuda_fp16.h>
#include <cstdint>
#include <math.h>

#define SDIM 2048
#define HDIM 2048
#define ANUM 16
#define NBLK 256
#define NTHR 512
#define CH   16        // chunks per 2048-half row
#define CCH  128       // halfs per chunk per stream
#define NSTG 4         // pipeline stages
#define TILEOFF 24576  // act staging bytes (3 x 8 KB)
#define DYNSMEM (TILEOFF + 16 * 4096)   // 90112 B

// ---------------- persistent state (__device__ globals only) ----------------
__device__ __align__(16) float g_h0[2][HDIM];
__device__ __align__(16) float g_h1[2][HDIM];
__device__ __align__(16) float g_c0[2][HDIM];
__device__ __align__(16) float g_c1[2][HDIM];
__device__ __align__(16) float g_pre0[4 * HDIM];    // layer0 preacts
__device__ __align__(16) float g_pre1[4 * HDIM];    // layer1 recurrent partial
__device__ __align__(16) float g_pre1f[4 * HDIM];   // layer1 full preacts
__device__ __align__(16) float g_logits[SDIM];
__device__ __align__(16) float g_partial[NBLK];
__device__ unsigned g_barCnt;
__device__ unsigned g_barGen;
__device__ __align__(16) __half g_wih16[2 * 4 * HDIM * HDIM];
__device__ __align__(16) __half g_whh16[2 * 4 * HDIM * HDIM];
__device__ __align__(16) __half g_wout16[SDIM * HDIM];

__device__ __forceinline__ float sigmoidf_(float x) {
    return 1.0f / (1.0f + __expf(-x));
}

__device__ __forceinline__ void cp8(uint32_t dst, const void* src) {
    asm volatile("cp.async.ca.shared.global [%0], [%1], 8;"
                 :: "r"(dst), "l"(src) : "memory");
}
#define CP_COMMIT() asm volatile("cp.async.commit_group;" ::: "memory")
#define CP_WAIT2()  asm volatile("cp.async.wait_group 2;"  ::: "memory")

// 4 half-weights (uint2) dot 4 floats (float4) into two accumulators.
__device__ __forceinline__ void dot4(uint2 w, float4 a, float& p, float& q) {
    __half2 h0 = *reinterpret_cast<__half2*>(&w.x);
    __half2 h1 = *reinterpret_cast<__half2*>(&w.y);
    float2 f0 = __half22float2(h0);
    float2 f1 = __half22float2(h1);
    p = fmaf(f0.x, a.x, p); q = fmaf(f0.y, a.y, q);
    p = fmaf(f1.x, a.z, p); q = fmaf(f1.y, a.w, q);
}

// Sense-reversing grid barrier. ALL NBLK blocks must be co-resident.
__device__ __forceinline__ void gridbar() {
    __threadfence();
    __syncthreads();
    if (threadIdx.x == 0) {
        unsigned g = *((volatile unsigned*)&g_barGen);
        unsigned a = atomicAdd(&g_barCnt, 1u);
        if (a == NBLK - 1) {
            g_barCnt = 0;
            __threadfence();
            atomicAdd(&g_barGen, 1u);
        } else {
            while (*((volatile unsigned*)&g_barGen) == g) __nanosleep(32);
        }
        __threadfence();
    }
    __syncthreads();
}

// ===========================================================================
// Persistent kernel: all 16 steps, 3 phases per step, grid barriers between.
// ===========================================================================
__global__ void __launch_bounds__(NTHR, 2) lstm_persistent(
    const __half* __restrict__ wih, const __half* __restrict__ whh,
    const __half* __restrict__ wout,
    const float* __restrict__ bih, const float* __restrict__ bhh,
    const float* __restrict__ bout,
    const float* __restrict__ x, float* __restrict__ out)
{
    extern __shared__ __align__(16) char smem[];
    float4* sX  = (float4*)smem;        // 512 float4: input / h0new / h1new
    float4* sH0 = sX + 512;             // h0_in (phase A)
    float4* sH1 = sH0 + 512;            // h1_in (phase A)
    __shared__ float s_inv, s_part[16], s_e[8];

    const int t = threadIdx.x, warp = t >> 5, lane = t & 31;
    const int W = blockIdx.x * 16 + warp;            // global warp id [0,4096)
    // cp.async destination base: per-warp tile + per-lane 8B slot  <-- R8 fix
    const uint32_t tb = (uint32_t)__cvta_generic_to_shared(smem)
                        + TILEOFF + warp * 4096 + lane * 8;
    const char* tbp = smem + TILEOFF + warp * 4096;

    const size_t L = (size_t)4 * HDIM * HDIM;
    const __half* Wih0 = wih;
    const __half* Whh0 = whh;
    const __half* Wih1 = wih + L;
    const __half* Whh1 = whh + L;

    const int a0 = 2 * W;   // flat row pair for phases A (both types) and B
    const __half* wiA = Wih0 + (size_t)a0 * HDIM;
    const __half* whA = Whh0 + (size_t)a0 * HDIM;
    const __half* wB  = Whh1 + (size_t)a0 * HDIM;
    const __half* wC2 = Wih1 + (size_t)a0 * HDIM;
    const int rc = W >> 1, chalf = W & 1;            // phase C: half-row each
    const __half* wD = wout + (size_t)rc * HDIM + chalf * 8 * CCH;

    // initial phase-A prologue (weights only; overlaps everything below)
    #pragma unroll
    for (int st = 0; st < NSTG - 1; st++) {
        uint32_t d = tb + st * 1024;
        cp8(d,       wiA + st * CCH + lane * 4);
        cp8(d + 256, whA + st * CCH + lane * 4);
        cp8(d + 512, wiA + HDIM + st * CCH + lane * 4);
        cp8(d + 768, whA + HDIM + st * CCH + lane * 4);
        CP_COMMIT();
    }

    for (int s = 0; s < ANUM; s++) {
        const int par = s & 1;
        const float* h0r = g_h0[par]; float* h0w = g_h0[par ^ 1];
        const float* h1r = g_h1[par]; float* h1w = g_h1[par ^ 1];
        const float* c0r = g_c0[par]; float* c0w = g_c0[par ^ 1];
        const float* c1r = g_c1[par]; float* c1w = g_c1[par ^ 1];

        // ================= phase A staging =================
        if (s > 0) {
            if (warp == 0) {
                float sum = 0.f;
                #pragma unroll
                for (int j = 0; j < 8; j++) sum += g_partial[lane + 32 * j];
                #pragma unroll
                for (int o = 16; o > 0; o >>= 1)
                    sum += __shfl_xor_sync(~0u, sum, o);
                if (lane == 0) s_inv = 1.f / sum;
            }
            __syncthreads();
            const float inv = s_inv;
            float4 lg = ((const float4*)g_logits)[t];
            float4 v;
            v.x = __expf(lg.x) * inv; v.y = __expf(lg.y) * inv;
            v.z = __expf(lg.z) * inv; v.w = __expf(lg.w) * inv;
            sX[t] = v;
            if (blockIdx.x == 0)
                ((float4*)(out + (size_t)(s - 1) * SDIM))[t] = v;
        } else {
            sX[t] = ((const float4*)x)[t];
        }
        sH0[t] = ((const float4*)h0r)[t];
        sH1[t] = ((const float4*)h1r)[t];
        __syncthreads();

        // ---- phase A typeA: layer0 rows a0, a0+1 (Wih0 + Whh0) ----
        float p0 = 0.f, q0 = 0.f, p1 = 0.f, q1 = 0.f;
        #pragma unroll 4
        for (int c = 0; c < CH; c++) {
            CP_WAIT2();
            float4 ax = sX[c * 32 + lane];
            float4 ah = sH0[c * 32 + lane];
            const char* tp = tbp + (c & 3) * 1024;
            uint2 w0 = *(const uint2*)(tp + lane * 8);
            uint2 w1 = *(const uint2*)(tp + 256 + lane * 8);
            uint2 w2 = *(const uint2*)(tp + 512 + lane * 8);
            uint2 w3 = *(const uint2*)(tp + 768 + lane * 8);
            dot4(w0, ax, p0, q0); dot4(w1, ah, p0, q0);
            dot4(w2, ax, p1, q1); dot4(w3, ah, p1, q1);
            const int nc = c + NSTG - 1;
            if (nc < CH) {
                uint32_t d = tb + (nc & 3) * 1024;
                cp8(d,       wiA + nc * CCH + lane * 4);
                cp8(d + 256, whA + nc * CCH + lane * 4);
                cp8(d + 512, wiA + HDIM + nc * CCH + lane * 4);
                cp8(d + 768, whA + HDIM + nc * CCH + lane * 4);
            }
            CP_COMMIT();
        }
        {
            float v0 = p0 + q0, v1 = p1 + q1;
            #pragma unroll
            for (int o = 16; o > 0; o >>= 1) {
                v0 += __shfl_xor_sync(~0u, v0, o);
                v1 += __shfl_xor_sync(~0u, v1, o);
            }
            if (lane == 0) {
                g_pre0[a0]     = v0 + bih[a0] + bhh[a0];
                g_pre0[a0 + 1] = v1 + bih[a0 + 1] + bhh[a0 + 1];
            }
        }

        // ---- phase A typeB: layer1 recurrent rows a0, a0+1 (Whh1) ----
        #pragma unroll
        for (int st = 0; st < NSTG - 1; st++) {
            uint32_t d = tb + st * 1024;
            cp8(d,       wB + st * CCH + lane * 4);
            cp8(d + 256, wB + HDIM + st * CCH + lane * 4);
            CP_COMMIT();
        }
        p0 = 0.f; q0 = 0.f; p1 = 0.f; q1 = 0.f;
        #pragma unroll 4
        for (int c = 0; c < CH; c++) {
            CP_WAIT2();
            float4 ah = sH1[c * 32 + lane];
            const char* tp = tbp + (c & 3) * 1024;
            uint2 w0 = *(const uint2*)(tp + lane * 8);
            uint2 w1 = *(const uint2*)(tp + 256 + lane * 8);
            dot4(w0, ah, p0, q0);
            dot4(w1, ah, p1, q1);
            const int nc = c + NSTG - 1;
            if (nc < CH) {
                uint32_t d = tb + (nc & 3) * 1024;
                cp8(d,       wB + nc * CCH + lane * 4);
                cp8(d + 256, wB + HDIM + nc * CCH + lane * 4);
            }
            CP_COMMIT();
        }
        {
            float v0 = p0 + q0, v1 = p1 + q1;
            #pragma unroll
            for (int o = 16; o > 0; o >>= 1) {
                v0 += __shfl_xor_sync(~0u, v0, o);
                v1 += __shfl_xor_sync(~0u, v1, o);
            }
            if (lane == 0) {
                g_pre1[a0]     = v0 + bih[4 * HDIM + a0] + bhh[4 * HDIM + a0];
                g_pre1[a0 + 1] = v1 + bih[4 * HDIM + a0 + 1] + bhh[4 * HDIM + a0 + 1];
            }
        }

        // prefetch phase B weights across the barrier
        #pragma unroll
        for (int st = 0; st < NSTG - 1; st++) {
            uint32_t d = tb + st * 1024;
            cp8(d,       wC2 + st * CCH + lane * 4);
            cp8(d + 256, wC2 + HDIM + st * CCH + lane * 4);
            CP_COMMIT();
        }
        gridbar();

        // ================= phase B: layer1 Wih + pointwise =================
        #pragma unroll
        for (int j = 0; j < 4; j++) {
            int u = t + j * 512;
            float gi = g_pre0[u],        gf = g_pre0[2048 + u];
            float gg = g_pre0[4096 + u], go = g_pre0[6144 + u];
            float cn = sigmoidf_(gf) * c0r[u] + sigmoidf_(gi) * tanhf(gg);
            float h  = sigmoidf_(go) * tanhf(cn);
            ((float*)sX)[u] = h;
            if (blockIdx.x == 0) { c0w[u] = cn; h0w[u] = h; }
        }
        __syncthreads();

        p0 = 0.f; q0 = 0.f; p1 = 0.f; q1 = 0.f;
        #pragma unroll 4
        for (int c = 0; c < CH; c++) {
            CP_WAIT2();
            float4 ah = sX[c * 32 + lane];
            const char* tp = tbp + (c & 3) * 1024;
            uint2 w0 = *(const uint2*)(tp + lane * 8);
            uint2 w1 = *(const uint2*)(tp + 256 + lane * 8);
            dot4(w0, ah, p0, q0);
            dot4(w1, ah, p1, q1);
            const int nc = c + NSTG - 1;
            if (nc < CH) {
                uint32_t d = tb + (nc & 3) * 1024;
                cp8(d,       wC2 + nc * CCH + lane * 4);
                cp8(d + 256, wC2 + HDIM + nc * CCH + lane * 4);
            }
            CP_COMMIT();
        }
        {
            float v0 = p0 + q0, v1 = p1 + q1;
            #pragma unroll
            for (int o = 16; o > 0; o >>= 1) {
                v0 += __shfl_xor_sync(~0u, v0, o);
                v1 += __shfl_xor_sync(~0u, v1, o);
            }
            if (lane == 0) {
                g_pre1f[a0]     = v0 + g_pre1[a0];
                g_pre1f[a0 + 1] = v1 + g_pre1[a0 + 1];
            }
        }

        // prefetch phase C weights across the barrier
        #pragma unroll
        for (int st = 0; st < NSTG - 1; st++) {
            cp8(tb + st * 1024, wD + st * CCH + lane * 4);
            CP_COMMIT();
        }
        gridbar();

        // ================= phase C: logits + pointwise =================
        #pragma unroll
        for (int j = 0; j < 4; j++) {
            int u = t + j * 512;
            float gi = g_pre1f[u],        gf = g_pre1f[2048 + u];
            float gg = g_pre1f[4096 + u], go = g_pre1f[6144 + u];
            float cn = sigmoidf_(gf) * c1r[u] + sigmoidf_(gi) * tanhf(gg);
            float h  = sigmoidf_(go) * tanhf(cn);
            ((float*)sX)[u] = h;
            if (blockIdx.x == 0) { c1w[u] = cn; h1w[u] = h; }
        }
        __syncthreads();

        p0 = 0.f; q0 = 0.f;
        #pragma unroll 4
        for (int c = 0; c < 8; c++) {
            CP_WAIT2();
            float4 a = sX[(chalf * 8 + c) * 32 + lane];
            uint2 w = *(const uint2*)(tbp + (c & 3) * 1024 + lane * 8);
            dot4(w, a, p0, q0);
            const int nc = c + NSTG - 1;
            if (nc < 8) cp8(tb + (nc & 3) * 1024, wD + nc * CCH + lane * 4);
            CP_COMMIT();
        }
        {
            float v0 = p0 + q0;
            #pragma unroll
            for (int o = 16; o > 0; o >>= 1)
                v0 += __shfl_xor_sync(~0u, v0, o);
            if (lane == 0) s_part[warp] = v0;
        }
        __syncthreads();
        if ((warp & 1) == 0 && lane == 0) {
            float tot = s_part[warp] + s_part[warp + 1];
            float lg = tot + bout[rc];
            g_logits[rc] = lg;
            s_e[warp >> 1] = __expf(lg);
        }
        __syncthreads();
        if (t == 0) {
            float se = 0.f;
            #pragma unroll
            for (int j = 0; j < 8; j++) se += s_e[j];
            g_partial[blockIdx.x] = se;
        }

        // prefetch next step's phase A weights across the barrier
        if (s < ANUM - 1) {
            #pragma unroll
            for (int st = 0; st < NSTG - 1; st++) {
                uint32_t d = tb + st * 1024;
                cp8(d,       wiA + st * CCH + lane * 4);
                cp8(d + 256, whA + st * CCH + lane * 4);
                cp8(d + 512, wiA + HDIM + st * CCH + lane * 4);
                cp8(d + 768, whA + HDIM + st * CCH + lane * 4);
                CP_COMMIT();
            }
        }
        gridbar();
    }

    // final softmax: output row ANUM-1 (block 0 only)
    if (blockIdx.x == 0) {
        if (warp == 0) {
            float sum = 0.f;
            #pragma unroll
            for (int j = 0; j < 8; j++) sum += g_partial[lane + 32 * j];
            #pragma unroll
            for (int o = 16; o > 0; o >>= 1)
                sum += __shfl_xor_sync(~0u, sum, o);
            if (lane == 0) s_inv = 1.f / sum;
        }
        __syncthreads();
        const float inv = s_inv;
        float4 lg = ((const float4*)g_logits)[t];
        float4 v;
        v.x = __expf(lg.x) * inv; v.y = __expf(lg.y) * inv;
        v.z = __expf(lg.z) * inv; v.w = __expf(lg.w) * inv;
        ((float4*)(out + (size_t)(ANUM - 1) * SDIM))[t] = v;
    }
}

// ===========================================================================
// One-shot fp32 -> fp16 conversion over all three weight arrays.
// ===========================================================================
__global__ void __launch_bounds__(256) cvt_all(
    const float* __restrict__ a, __half* __restrict__ da, int na,
    const float* __restrict__ b, __half* __restrict__ db, int nb,
    const float* __restrict__ c, __half* __restrict__ dc, int ncnt)
{
    const int total = (na + nb + ncnt) >> 3;
    const int stride = gridDim.x * blockDim.x;
    for (int u = blockIdx.x * blockDim.x + threadIdx.x; u < total; u += stride) {
        const int i = u << 3;
        const float* s; __half* d;
        if (i < na)           { s = a + i;             d = da + i; }
        else if (i < na + nb) { s = b + (i - na);      d = db + (i - na); }
        else                  { s = c + (i - na - nb); d = dc + (i - na - nb); }
        float4 x0 = *(const float4*)s;
        float4 x1 = *(const float4*)(s + 4);
        __half2 h0 = __floats2half2_rn(x0.x, x0.y);
        __half2 h1 = __floats2half2_rn(x0.z, x0.w);
        __half2 h2 = __floats2half2_rn(x1.x, x1.y);
        __half2 h3 = __floats2half2_rn(x1.z, x1.w);
        uint4 o;
        o.x = *(unsigned*)&h0; o.y = *(unsigned*)&h1;
        o.z = *(unsigned*)&h2; o.w = *(unsigned*)&h3;
        *(uint4*)d = o;
    }
}

// ---------------------------------------------------------------------------
extern "C" void kernel_launch(void* const* d_in, const int* in_sizes, int n_in,
                              void* d_out, int out_size)
{
    const float* x    = (const float*)d_in[0];
    const float* Wih  = (const float*)d_in[1];
    const float* Whh  = (const float*)d_in[2];
    const float* bih  = (const float*)d_in[3];
    const float* bhh  = (const float*)d_in[4];
    const float* Wout = (const float*)d_in[5];
    const float* bout = (const float*)d_in[6];
    float* out = (float*)d_out;

    float *h0, *h1, *c0, *c1;
    unsigned *bc, *bg;
    __half *wih16, *whh16, *wout16;
    cudaGetSymbolAddress((void**)&h0,     g_h0);
    cudaGetSymbolAddress((void**)&h1,     g_h1);
    cudaGetSymbolAddress((void**)&c0,     g_c0);
    cudaGetSymbolAddress((void**)&c1,     g_c1);
    cudaGetSymbolAddress((void**)&bc,     g_barCnt);
    cudaGetSymbolAddress((void**)&bg,     g_barGen);
    cudaGetSymbolAddress((void**)&wih16,  g_wih16);
    cudaGetSymbolAddress((void**)&whh16,  g_whh16);
    cudaGetSymbolAddress((void**)&wout16, g_wout16);

    cudaFuncSetAttribute(lstm_persistent,
                         cudaFuncAttributeMaxDynamicSharedMemorySize, DYNSMEM);

    // zero step-0 state and barrier
    cudaMemsetAsync(h0, 0, sizeof(float) * HDIM);   // g_h0[0]
    cudaMemsetAsync(h1, 0, sizeof(float) * HDIM);   // g_h1[0]
    cudaMemsetAsync(c0, 0, sizeof(float) * HDIM);   // g_c0[0]
    cudaMemsetAsync(c1, 0, sizeof(float) * HDIM);   // g_c1[0]
    cudaMemsetAsync(bc, 0, sizeof(unsigned));
    cudaMemsetAsync(bg, 0, sizeof(unsigned));

    const int NW = 2 * 4 * HDIM * HDIM;
    const int NO = SDIM * HDIM;
    cvt_all<<<2048, 256>>>(Wih, wih16, NW, Whh, whh16, NW, Wout, wout16, NO);

    lstm_persistent<<<NBLK, NTHR, DYNSMEM>>>(
        wih16, whh16, wout16, bih, bhh, bout, x, out);
}

// round 11
// speedup vs baseline: 1.3573x; 1.3573x over previous
#include <cuda_runtime.h>
#include <cuda_fp16.h>
#include <cstdint>
#include <math.h>

#define SDIM 2048
#define HDIM 2048
#define ANUM 16
#define NB_A 256      // K1 type-A blocks (layer0 gates, 8 units each)
#define NB_B 256      // K1 type-B blocks (layer1 recurrent, 32 rows each)
#define NB_3 256      // K3 blocks (8 logit rows each, half-row per warp)
#define CH   8        // chunks per row (2048 / 256)
#define CC   256      // halfs per chunk per row per matrix
#define NSTG 3        // pipeline stages (K1/K2)

// Persistent scratch
__device__ __align__(16) float g_h0[2][HDIM];
__device__ __align__(16) float g_h1[2][HDIM];
__device__ __align__(16) float g_c[2][HDIM];
__device__ __align__(16) float g_pre1[4 * HDIM];
__device__ __align__(16) float g_logits[SDIM];
__device__ __align__(16) float g_partial[NB_3];
__device__ __align__(16) __half g_wih16[2 * 4 * HDIM * HDIM];
__device__ __align__(16) __half g_whh16[2 * 4 * HDIM * HDIM];
__device__ __align__(16) __half g_wout16[SDIM * HDIM];

__device__ __forceinline__ float sigmoidf_(float x) {
    return 1.0f / (1.0f + __expf(-x));
}

__device__ __forceinline__ void cp16(uint32_t dst, const void* src) {
    asm volatile("cp.async.cg.shared.global [%0], [%1], 16;"
                 :: "r"(dst), "l"(src) : "memory");
}
#define CP_COMMIT() asm volatile("cp.async.commit_group;" ::: "memory")
#define CP_WAIT1()  asm volatile("cp.async.wait_group 1;"  ::: "memory")

// 8 half-weights (uint4) dot 8 floats (two float4), into two accumulators.
__device__ __forceinline__ void dot8(uint4 w, float4 lo, float4 hi,
                                     float& p, float& q) {
    const __half2* hp = reinterpret_cast<const __half2*>(&w);
    float2 f0 = __half22float2(hp[0]);
    float2 f1 = __half22float2(hp[1]);
    float2 f2 = __half22float2(hp[2]);
    float2 f3 = __half22float2(hp[3]);
    p = fmaf(f0.x, lo.x, p); q = fmaf(f0.y, lo.y, q);
    p = fmaf(f1.x, lo.z, p); q = fmaf(f1.y, lo.w, q);
    p = fmaf(f2.x, hi.x, p); q = fmaf(f2.y, hi.y, q);
    p = fmaf(f3.x, hi.z, p); q = fmaf(f3.y, hi.w, q);
}

// ===========================================================================
// K1: type-A blocks = layer-0 full gates (+inline softmax input, step>0);
//     type-B blocks = layer-1 recurrent partials -> pre1.
// 512 threads, 2 rows/warp. Per-warp private cp.async pipeline.
// ===========================================================================
template<int FIRST>
__global__ void __launch_bounds__(512, 2) step_k1(
    const __half* __restrict__ Wih0, const __half* __restrict__ Whh0,
    const __half* __restrict__ Whh1,
    const float* __restrict__ bih0, const float* __restrict__ bhh0,
    const float* __restrict__ bih1, const float* __restrict__ bhh1,
    const float* __restrict__ xin,
    const float* __restrict__ logits, const float* __restrict__ partials,
    float* __restrict__ out_prev,
    const float* __restrict__ h0_in, float* __restrict__ h0_out,
    const float* __restrict__ h1_in,
    float* __restrict__ c0, float* __restrict__ pre1)
{
    extern __shared__ __align__(16) char smem[];
    float4* sIn0 = (float4*)smem;
    float4* sIn1 = sIn0 + 256;
    float4* sH0  = sIn1 + 256;
    float4* sH1  = sH0 + 256;
    __half* tiles = (__half*)(smem + 16384);
    __shared__ float s_g[32];
    __shared__ float s_inv;

    const int t = threadIdx.x, warp = t >> 5, lane = t & 31;
    const bool typeA = (blockIdx.x < NB_A);
    const uint32_t smemU = (uint32_t)__cvta_generic_to_shared(smem);
    const uint32_t tileU = smemU + 16384 + warp * 6144 + lane * 16;
    const __half* tileh  = tiles + warp * 3072;

    int rg0;
    const __half *rA0, *rB0;
    if (typeA) {
        const int i0 = 2 * warp;
        rg0 = (i0 >> 3) * HDIM + blockIdx.x * 8 + (i0 & 7);
        rA0 = Wih0 + (size_t)rg0 * HDIM;
        rB0 = Whh0 + (size_t)rg0 * HDIM;
    } else {
        rg0 = (blockIdx.x - NB_A) * 32 + 2 * warp;
        rA0 = Whh1 + (size_t)rg0 * HDIM;
        rB0 = nullptr;
    }

    // prologue
    if (typeA) {
        #pragma unroll
        for (int s = 0; s < NSTG - 1; s++) {
            const uint32_t d = tileU + s * 2048;
            cp16(d,        rA0 + s * CC + lane * 8);
            cp16(d + 512,  rA0 + HDIM + s * CC + lane * 8);
            cp16(d + 1024, rB0 + s * CC + lane * 8);
            cp16(d + 1536, rB0 + HDIM + s * CC + lane * 8);
            CP_COMMIT();
        }
    } else {
        #pragma unroll
        for (int s = 0; s < NSTG - 1; s++) {
            const uint32_t d = tileU + s * 2048;
            cp16(d,       rA0 + s * CC + lane * 8);
            cp16(d + 512, rA0 + HDIM + s * CC + lane * 8);
            CP_COMMIT();
        }
    }

    // activation staging (overlaps cp.async latency)
    if (typeA) {
        if (!FIRST) {
            if (warp == 0) {
                float s = 0.0f;
                #pragma unroll
                for (int j = 0; j < 8; j++) s += partials[lane + j * 32];
                #pragma unroll
                for (int o = 16; o > 0; o >>= 1)
                    s += __shfl_xor_sync(0xffffffffu, s, o);
                if (lane == 0) s_inv = 1.0f / s;
            }
            __syncthreads();
        }
        float4 v;
        if (FIRST) {
            v = ((const float4*)xin)[t];
        } else {
            float4 lg = ((const float4*)logits)[t];
            const float inv = s_inv;
            v.x = __expf(lg.x) * inv;
            v.y = __expf(lg.y) * inv;
            v.z = __expf(lg.z) * inv;
            v.w = __expf(lg.w) * inv;
            if (blockIdx.x == 0) ((float4*)out_prev)[t] = v;
        }
        ((t & 1) ? sIn1 : sIn0)[t >> 1] = v;
        float4 hv = ((const float4*)h0_in)[t];
        ((t & 1) ? sH1 : sH0)[t >> 1] = hv;
    } else {
        float4 hv = ((const float4*)h1_in)[t];
        ((t & 1) ? sIn1 : sIn0)[t >> 1] = hv;
    }
    __syncthreads();

    // streaming loop
    float p0 = 0.f, q0 = 0.f, p1 = 0.f, q1 = 0.f;
    if (typeA) {
        #pragma unroll
        for (int c = 0; c < CH; c++) {
            CP_WAIT1();
            const int st = c % NSTG;
            const float4 a0 = sIn0[c * 32 + lane], a1 = sIn1[c * 32 + lane];
            const float4 b0 = sH0[c * 32 + lane],  b1 = sH1[c * 32 + lane];
            const __half* tp = tileh + st * 1024;
            uint4 wA0 = *(const uint4*)(tp +       lane * 8);
            uint4 wA1 = *(const uint4*)(tp + 256 + lane * 8);
            uint4 wB0 = *(const uint4*)(tp + 512 + lane * 8);
            uint4 wB1 = *(const uint4*)(tp + 768 + lane * 8);
            dot8(wA0, a0, a1, p0, q0);
            dot8(wB0, b0, b1, p0, q0);
            dot8(wA1, a0, a1, p1, q1);
            dot8(wB1, b0, b1, p1, q1);
            const int nc = c + NSTG - 1;
            if (nc < CH) {
                const uint32_t d = tileU + (nc % NSTG) * 2048;
                cp16(d,        rA0 + nc * CC + lane * 8);
                cp16(d + 512,  rA0 + HDIM + nc * CC + lane * 8);
                cp16(d + 1024, rB0 + nc * CC + lane * 8);
                cp16(d + 1536, rB0 + HDIM + nc * CC + lane * 8);
            }
            CP_COMMIT();
        }
    } else {
        #pragma unroll
        for (int c = 0; c < CH; c++) {
            CP_WAIT1();
            const int st = c % NSTG;
            const float4 a0 = sIn0[c * 32 + lane], a1 = sIn1[c * 32 + lane];
            const __half* tp = tileh + st * 1024;
            uint4 wA0 = *(const uint4*)(tp +       lane * 8);
            uint4 wA1 = *(const uint4*)(tp + 256 + lane * 8);
            dot8(wA0, a0, a1, p0, q0);
            dot8(wA1, a0, a1, p1, q1);
            const int nc = c + NSTG - 1;
            if (nc < CH) {
                const uint32_t d = tileU + (nc % NSTG) * 2048;
                cp16(d,       rA0 + nc * CC + lane * 8);
                cp16(d + 512, rA0 + HDIM + nc * CC + lane * 8);
            }
            CP_COMMIT();
        }
    }

    // reduce + epilogue
    float v0 = p0 + q0, v1 = p1 + q1;
    #pragma unroll
    for (int o = 16; o > 0; o >>= 1) {
        v0 += __shfl_xor_sync(0xffffffffu, v0, o);
        v1 += __shfl_xor_sync(0xffffffffu, v1, o);
    }
    if (typeA) {
        if (lane == 0) {
            s_g[2 * warp]     = v0 + bih0[rg0] + bhh0[rg0];
            s_g[2 * warp + 1] = v1 + bih0[rg0 + 1] + bhh0[rg0 + 1];
        }
        __syncthreads();
        if (t < 8) {
            const int u = blockIdx.x * 8 + t;
            float iv = sigmoidf_(s_g[t]);
            float fv = sigmoidf_(s_g[8 + t]);
            float gv = tanhf(s_g[16 + t]);
            float ov = sigmoidf_(s_g[24 + t]);
            float cn = fv * c0[u] + iv * gv;
            c0[u]     = cn;
            h0_out[u] = ov * tanhf(cn);
        }
    } else {
        if (lane == 0) {
            pre1[rg0]     = v0 + bih1[rg0] + bhh1[rg0];
            pre1[rg0 + 1] = v1 + bih1[rg0 + 1] + bhh1[rg0 + 1];
        }
    }
}

// ===========================================================================
// K2: layer-1 input half (Wih1) + pointwise. 256 blocks, 2 rows/warp.
// ===========================================================================
__global__ void __launch_bounds__(512, 2) step_k2(
    const __half* __restrict__ Wih1,
    const float* __restrict__ pre1,
    const float* __restrict__ h0_new,
    float* __restrict__ h1_out, float* __restrict__ c1)
{
    extern __shared__ __align__(16) char smem[];
    float4* sA0 = (float4*)smem;
    float4* sA1 = sA0 + 256;
    __half* tiles = (__half*)(smem + 8192);
    __shared__ float s_g[32];

    const int t = threadIdx.x, warp = t >> 5, lane = t & 31;
    const uint32_t smemU = (uint32_t)__cvta_generic_to_shared(smem);
    const uint32_t tileU = smemU + 8192 + warp * 3072 + lane * 16;
    const __half* tileh  = tiles + warp * 1536;

    const int i0 = 2 * warp;
    const int rg0 = (i0 >> 3) * HDIM + blockIdx.x * 8 + (i0 & 7);
    const __half* rA0 = Wih1 + (size_t)rg0 * HDIM;

    #pragma unroll
    for (int s = 0; s < NSTG - 1; s++) {
        const uint32_t d = tileU + s * 1024;
        cp16(d,       rA0 + s * CC + lane * 8);
        cp16(d + 512, rA0 + HDIM + s * CC + lane * 8);
        CP_COMMIT();
    }

    {
        float4 hv = ((const float4*)h0_new)[t];
        ((t & 1) ? sA1 : sA0)[t >> 1] = hv;
    }
    __syncthreads();

    float p0 = 0.f, q0 = 0.f, p1 = 0.f, q1 = 0.f;
    #pragma unroll
    for (int c = 0; c < CH; c++) {
        CP_WAIT1();
        const int st = c % NSTG;
        const float4 a0 = sA0[c * 32 + lane], a1 = sA1[c * 32 + lane];
        const __half* tp = tileh + st * 512;
        uint4 w0 = *(const uint4*)(tp +       lane * 8);
        uint4 w1 = *(const uint4*)(tp + 256 + lane * 8);
        dot8(w0, a0, a1, p0, q0);
        dot8(w1, a0, a1, p1, q1);
        const int nc = c + NSTG - 1;
        if (nc < CH) {
            const uint32_t d = tileU + (nc % NSTG) * 1024;
            cp16(d,       rA0 + nc * CC + lane * 8);
            cp16(d + 512, rA0 + HDIM + nc * CC + lane * 8);
        }
        CP_COMMIT();
    }

    float v0 = p0 + q0, v1 = p1 + q1;
    #pragma unroll
    for (int o = 16; o > 0; o >>= 1) {
        v0 += __shfl_xor_sync(0xffffffffu, v0, o);
        v1 += __shfl_xor_sync(0xffffffffu, v1, o);
    }
    if (lane == 0) {
        s_g[2 * warp]     = v0 + pre1[rg0];
        s_g[2 * warp + 1] = v1 + pre1[rg0 + 1];
    }
    __syncthreads();
    if (t < 8) {
        const int u = blockIdx.x * 8 + t;
        float iv = sigmoidf_(s_g[t]);
        float fv = sigmoidf_(s_g[8 + t]);
        float gv = tanhf(s_g[16 + t]);
        float ov = sigmoidf_(s_g[24 + t]);
        float cn = fv * c1[u] + iv * gv;
        c1[u]     = cn;
        h1_out[u] = ov * tanhf(cn);
    }
}

// ===========================================================================
// K3 (redesigned): logits + per-block exp-sum partials.
// 256 blocks x 512 thr; HALF-ROW (2 KB) per warp, pair-combine in smem.
// All 4 chunks issued up-front; staged wait_group consumption.
// ===========================================================================
__global__ void __launch_bounds__(512, 2) step_k3(
    const __half* __restrict__ Wout,
    const float* __restrict__ bout,
    const float* __restrict__ h,
    float* __restrict__ logits,
    float* __restrict__ partials)
{
    extern __shared__ __align__(16) char smem[];
    float4* sA0 = (float4*)smem;
    float4* sA1 = sA0 + 256;
    __half* tiles = (__half*)(smem + 8192);
    __shared__ float s_part[16];
    __shared__ float s_e[8];

    const int t = threadIdx.x, warp = t >> 5, lane = t & 31;
    const uint32_t tileU = (uint32_t)__cvta_generic_to_shared(smem)
                           + 8192 + warp * 2048 + lane * 16;
    const __half* tileh = tiles + warp * 1024;

    const int row  = blockIdx.x * 8 + (warp >> 1);
    const int half = warp & 1;
    const __half* rA = Wout + (size_t)row * HDIM + half * 1024;

    // issue all 4 chunks immediately
    #pragma unroll
    for (int c = 0; c < 4; c++) {
        cp16(tileU + c * 512, rA + c * CC + lane * 8);
        CP_COMMIT();
    }

    {
        float4 hv = ((const float4*)h)[t];
        ((t & 1) ? sA1 : sA0)[t >> 1] = hv;
    }
    __syncthreads();

    float p = 0.f, q = 0.f;
    const int ab = half * 128;
    asm volatile("cp.async.wait_group 3;" ::: "memory");
    {
        uint4 w = *(const uint4*)(tileh + lane * 8);
        dot8(w, sA0[ab + lane], sA1[ab + lane], p, q);
    }
    asm volatile("cp.async.wait_group 2;" ::: "memory");
    {
        uint4 w = *(const uint4*)(tileh + 256 + lane * 8);
        dot8(w, sA0[ab + 32 + lane], sA1[ab + 32 + lane], p, q);
    }
    asm volatile("cp.async.wait_group 1;" ::: "memory");
    {
        uint4 w = *(const uint4*)(tileh + 512 + lane * 8);
        dot8(w, sA0[ab + 64 + lane], sA1[ab + 64 + lane], p, q);
    }
    asm volatile("cp.async.wait_group 0;" ::: "memory");
    {
        uint4 w = *(const uint4*)(tileh + 768 + lane * 8);
        dot8(w, sA0[ab + 96 + lane], sA1[ab + 96 + lane], p, q);
    }

    float v = p + q;
    #pragma unroll
    for (int o = 16; o > 0; o >>= 1)
        v += __shfl_xor_sync(0xffffffffu, v, o);
    if (lane == 0) s_part[warp] = v;
    __syncthreads();
    if ((warp & 1) == 0 && lane == 0) {
        float lg = s_part[warp] + s_part[warp + 1] + bout[row];
        logits[row] = lg;
        s_e[warp >> 1] = __expf(lg);
    }
    __syncthreads();
    if (t == 0) {
        float se = 0.f;
        #pragma unroll
        for (int j = 0; j < 8; j++) se += s_e[j];
        partials[blockIdx.x] = se;
    }
}

// ===========================================================================
// One-shot fp32 -> fp16 conversion over all three weight arrays.
// ===========================================================================
__global__ void __launch_bounds__(256) cvt_all(
    const float* __restrict__ a, __half* __restrict__ da, int na,
    const float* __restrict__ b, __half* __restrict__ db, int nb,
    const float* __restrict__ c, __half* __restrict__ dc, int ncnt)
{
    const int total = (na + nb + ncnt) >> 3;
    const int stride = gridDim.x * blockDim.x;
    for (int u = blockIdx.x * blockDim.x + threadIdx.x; u < total; u += stride) {
        const int i = u << 3;
        const float* s; __half* d;
        if (i < na)           { s = a + i;             d = da + i; }
        else if (i < na + nb) { s = b + (i - na);      d = db + (i - na); }
        else                  { s = c + (i - na - nb); d = dc + (i - na - nb); }
        float4 x0 = *(const float4*)s;
        float4 x1 = *(const float4*)(s + 4);
        __half2 h0 = __floats2half2_rn(x0.x, x0.y);
        __half2 h1 = __floats2half2_rn(x0.z, x0.w);
        __half2 h2 = __floats2half2_rn(x1.x, x1.y);
        __half2 h3 = __floats2half2_rn(x1.z, x1.w);
        uint4 o;
        o.x = *(unsigned*)&h0; o.y = *(unsigned*)&h1;
        o.z = *(unsigned*)&h2; o.w = *(unsigned*)&h3;
        *(uint4*)d = o;
    }
}

// Final step's softmax output row.
__global__ void __launch_bounds__(512) final_softmax_kernel(
    const float* __restrict__ logits,
    const float* __restrict__ partials,
    float* __restrict__ out_row)
{
    __shared__ float s_inv;
    const int t = threadIdx.x, warp = t >> 5, lane = t & 31;
    if (warp == 0) {
        float s = 0.0f;
        #pragma unroll
        for (int j = 0; j < 8; j++) s += partials[lane + j * 32];
        #pragma unroll
        for (int o = 16; o > 0; o >>= 1)
            s += __shfl_xor_sync(0xffffffffu, s, o);
        if (lane == 0) s_inv = 1.0f / s;
    }
    __syncthreads();
    const float inv = s_inv;
    float4 lg = ((const float4*)logits)[t];
    float4 v;
    v.x = __expf(lg.x) * inv;
    v.y = __expf(lg.y) * inv;
    v.z = __expf(lg.z) * inv;
    v.w = __expf(lg.w) * inv;
    ((float4*)out_row)[t] = v;
}

// ---------------------------------------------------------------------------
extern "C" void kernel_launch(void* const* d_in, const int* in_sizes, int n_in,
                              void* d_out, int out_size)
{
    const float* x    = (const float*)d_in[0];
    const float* Wih  = (const float*)d_in[1];
    const float* Whh  = (const float*)d_in[2];
    const float* bih  = (const float*)d_in[3];
    const float* bhh  = (const float*)d_in[4];
    const float* Wout = (const float*)d_in[5];
    const float* bout = (const float*)d_in[6];
    float* out = (float*)d_out;

    float *h0, *h1, *cbuf, *gl, *gp, *pre1;
    __half *wih16, *whh16, *wout16;
    cudaGetSymbolAddress((void**)&h0,     g_h0);
    cudaGetSymbolAddress((void**)&h1,     g_h1);
    cudaGetSymbolAddress((void**)&cbuf,   g_c);
    cudaGetSymbolAddress((void**)&gl,     g_logits);
    cudaGetSymbolAddress((void**)&gp,     g_partial);
    cudaGetSymbolAddress((void**)&pre1,   g_pre1);
    cudaGetSymbolAddress((void**)&wih16,  g_wih16);
    cudaGetSymbolAddress((void**)&whh16,  g_whh16);
    cudaGetSymbolAddress((void**)&wout16, g_wout16);

    const int SM_K1 = 16384 + 16 * 6144;   // 114688
    const int SM_K2 = 8192 + 16 * 3072;    // 57344
    const int SM_K3 = 8192 + 16 * 2048;    // 40960
    cudaFuncSetAttribute(step_k1<0>, cudaFuncAttributeMaxDynamicSharedMemorySize, SM_K1);
    cudaFuncSetAttribute(step_k1<1>, cudaFuncAttributeMaxDynamicSharedMemorySize, SM_K1);
    cudaFuncSetAttribute(step_k2,    cudaFuncAttributeMaxDynamicSharedMemorySize, SM_K2);
    cudaFuncSetAttribute(step_k3,    cudaFuncAttributeMaxDynamicSharedMemorySize, SM_K3);

    cudaMemsetAsync(h0, 0, sizeof(float) * HDIM);           // h0[0]
    cudaMemsetAsync(h1, 0, sizeof(float) * HDIM);           // h1[0]
    cudaMemsetAsync(cbuf, 0, sizeof(float) * 2 * HDIM);     // c0, c1

    const int NW = 2 * 4 * HDIM * HDIM;
    const int NO = SDIM * HDIM;
    cvt_all<<<2048, 256>>>(Wih, wih16, NW, Whh, whh16, NW, Wout, wout16, NO);

    const size_t wOffL = (size_t)4 * HDIM * HDIM;
    const size_t bOffL = (size_t)4 * HDIM;

    for (int s = 0; s < ANUM; s++) {
        const int r = s & 1;
        const int w = 1 - r;
        float* h0_in  = h0 + (size_t)r * HDIM;
        float* h0_out = h0 + (size_t)w * HDIM;
        float* h1_in  = h1 + (size_t)r * HDIM;
        float* h1_out = h1 + (size_t)w * HDIM;

        if (s == 0) {
            step_k1<1><<<NB_A + NB_B, 512, SM_K1>>>(
                wih16, whh16, whh16 + wOffL,
                bih, bhh, bih + bOffL, bhh + bOffL,
                x, nullptr, nullptr, nullptr,
                h0_in, h0_out, h1_in, cbuf, pre1);
        } else {
            step_k1<0><<<NB_A + NB_B, 512, SM_K1>>>(
                wih16, whh16, whh16 + wOffL,
                bih, bhh, bih + bOffL, bhh + bOffL,
                nullptr, gl, gp, out + (size_t)(s - 1) * SDIM,
                h0_in, h0_out, h1_in, cbuf, pre1);
        }
        step_k2<<<NB_A, 512, SM_K2>>>(
            wih16 + wOffL, pre1, h0_out, h1_out, cbuf + HDIM);
        step_k3<<<NB_3, 512, SM_K3>>>(
            wout16, bout, h1_out, gl, gp);
    }

    final_softmax_kernel<<<1, 512>>>(gl, gp, out + (size_t)(ANUM - 1) * SDIM);
}